// round 13
// baseline (speedup 1.0000x reference)
#include <cuda_runtime.h>
#include <cuda_fp16.h>
#include <cstdint>

// ---------------------------------------------------------------------------
// Tree NN as 7 GEMMs: X_{l+1}[M,128] = tanh(X_l.view(M,256) @ W^T + b).
// concat(left,right) == reinterpret of row-major [2M,128] as [M,256].
// Precision: activations fp16, W split fp16 hi/lo: D = A*Wh + A*Wl (f32 acc).
// R12: multi-tile per-level kernels. Each CTA owns an N-half (64 cols of W,
// 64KB resident in smem, staged ONCE) and loops over m-tiles (128 rows).
// A chunks (128x64 fp16, 16KB, XOR-swizzled 128B rows) in a depth-3 cp.async
// ring. 2 CTAs/SM. Warp tile 32x32 (4Mw x 2Nw), same fragment code as R11.
// (tcgen05 unavailable: harness compiles for plain sm_103.)
// ---------------------------------------------------------------------------

#define SM_BIAS 0
#define SM_W    512                      // 8 planes (4 chunks x hi/lo) x 8192B
#define SM_A    (SM_W + 65536)           // 3 bufs x 16384B
#define SMEM_BYTES (SM_A + 3 * 16384)    // 115200 B -> 2 CTAs/SM

__device__ __half gA0[262144u * 128u];   // 64 MiB: L1,3,5,7 outputs
__device__ __half gA1[131072u * 128u];   // 32 MiB: L2,4,6 outputs
__device__ __half gWh[128 * 256];
__device__ __half gWl[128 * 256];
__device__ int g_tok64;

__global__ void detect_tok_kernel(const unsigned int* __restrict__ t) {
    if (threadIdx.x == 0) {
        int all_zero = 1;
        for (int i = 1; i < 256; i += 2) all_zero &= (t[i] == 0u);
        g_tok64 = all_zero;
    }
}
__global__ void wsplit_kernel(const float* __restrict__ Wt) {
    int i = blockIdx.x * 256 + threadIdx.x;
    if (i < 128 * 256) {
        float v = Wt[i];
        __half h = __float2half_rn(v);
        gWh[i] = h;
        gWl[i] = __float2half_rn(v - __half2float(h));
    }
}

__device__ __forceinline__ float fast_tanh(float x) {
    float e = __expf(2.0f * x);
    return 1.0f - __fdividef(2.0f, e + 1.0f);
}
__device__ __forceinline__ uint32_t packh2(float x0, float x1) {
    __half h0 = __float2half_rn(x0), h1 = __float2half_rn(x1);
    return (uint32_t)__half_as_ushort(h0) | ((uint32_t)__half_as_ushort(h1) << 16);
}
__device__ __forceinline__ void mma_fp16(float* d, const uint32_t* a,
                                         const uint32_t* b) {
    asm volatile(
        "mma.sync.aligned.m16n8k16.row.col.f32.f16.f16.f32 "
        "{%0,%1,%2,%3}, {%4,%5,%6,%7}, {%8,%9}, {%0,%1,%2,%3};\n"
        : "+f"(d[0]), "+f"(d[1]), "+f"(d[2]), "+f"(d[3])
        : "r"(a[0]), "r"(a[1]), "r"(a[2]), "r"(a[3]), "r"(b[0]), "r"(b[1]));
}
__device__ __forceinline__ void ldsm4(uint32_t* r, uint32_t saddr) {
    asm volatile(
        "ldmatrix.sync.aligned.m8n8.x4.shared.b16 {%0,%1,%2,%3}, [%4];\n"
        : "=r"(r[0]), "=r"(r[1]), "=r"(r[2]), "=r"(r[3]) : "r"(saddr));
}
__device__ __forceinline__ void cpaA16(uint32_t dst, const void* src) {
    asm volatile("cp.async.cg.shared.global [%0], [%1], 16;" :: "r"(dst), "l"(src));
}
__device__ __forceinline__ void cpaW16(uint32_t dst, const void* src) {
    asm volatile("cp.async.ca.shared.global [%0], [%1], 16;" :: "r"(dst), "l"(src));
}
__device__ __forceinline__ void cpa_commit() { asm volatile("cp.async.commit_group;"); }
__device__ __forceinline__ void cpa_wait2() { asm volatile("cp.async.wait_group 2;"); }
__device__ __forceinline__ void cpa_wait0() { asm volatile("cp.async.wait_group 0;"); }

// swizzled byte offset within a plane of 128B rows: slot s (16B), row r
__device__ __forceinline__ uint32_t swz(int r, int s) {
    return (uint32_t)(r * 128 + ((s ^ (r & 7)) * 16));
}

// ---------------------------------------------------------------------------
// One level. grid = min(2*mtiles, 296). CTA = (nhalf = bid&1) x m-tile loop.
__global__ __launch_bounds__(256, 2) void tree_level_kernel(
    const void* __restrict__ tokens_raw,
    const float* __restrict__ emb,
    const float* __restrict__ bias,
    int first, int flip, int mtiles)
{
    extern __shared__ __align__(16) unsigned char smem[];
    const uint32_t sb = (uint32_t)__cvta_generic_to_shared(smem);
    const int tid  = threadIdx.x;
    const int lane = tid & 31;
    const int w    = tid >> 5;
    const int grid = gridDim.x;
    const int tiles = mtiles * 2;
    const int nh   = blockIdx.x & 1;          // constant (grid is even)
    const int tok64 = g_tok64;

    const __half* Ain = flip ? gA1 : gA0;
    __half* Aout      = flip ? gA0 : gA1;

    int nT = 0;
    for (int t = blockIdx.x; t < tiles; t += grid) nT++;
    const int J = nT * 4;

    // ---- bias + resident W half (staged once) ----
    if (tid < 128) ((float*)smem)[tid] = bias[tid];
    for (int i = tid; i < 4096; i += 256) {
        int cp = i >> 9, rem = i & 511;       // cp = chunk*2 + plane
        int r = rem >> 3, s = rem & 7;
        const __half* src = ((cp & 1) ? gWl : gWh)
                          + (nh * 64 + r) * 256 + (cp >> 1) * 64 + s * 8;
        cpaW16(sb + SM_W + cp * 8192 + swz(r, s), src);
    }
    cpa_commit();                              // group W

    // warp geometry: 4 warps M x 2 warps N, warp tile 32x32
    const int wm  = (w & 3) * 32;
    const int wnn = (w >> 2) * 32;
    const int la_row = lane & 15;
    const int la_s   = lane >> 4;              // A 16B-slot half
    const int lb_n   = ((lane >> 4) << 3) + (lane & 7);
    const int lb_s   = (lane >> 3) & 1;        // B 16B-slot half

    float acc[2][4][4] = {};

    auto m0_of = [&](int j) {
        return (int)(((unsigned)(blockIdx.x + (j >> 2) * grid)) >> 1) * 128;
    };

    auto doMMA = [&](int j) {
        const int c = j & 3;
        const uint32_t aB = sb + SM_A + (j % 3) * 16384;
        const uint32_t bH = sb + SM_W + (c * 2) * 8192;
        const uint32_t bL = bH + 8192;
#pragma unroll
        for (int ks = 0; ks < 4; ks++) {
            uint32_t ah[2][4], bh[2][4], bl[2][4];
#pragma unroll
            for (int mt = 0; mt < 2; mt++) {
                int r = wm + mt * 16 + la_row;
                ldsm4(ah[mt], aB + swz(r, ks * 2 + la_s));
            }
#pragma unroll
            for (int pr = 0; pr < 2; pr++) {
                int r = wnn + pr * 16 + lb_n;
                ldsm4(bh[pr], bH + swz(r, ks * 2 + lb_s));
                ldsm4(bl[pr], bL + swz(r, ks * 2 + lb_s));
            }
#pragma unroll
            for (int mt = 0; mt < 2; mt++)
#pragma unroll
                for (int nt = 0; nt < 4; nt++) {
                    const uint32_t* bhp = &bh[nt >> 1][(nt & 1) * 2];
                    const uint32_t* blp = &bl[nt >> 1][(nt & 1) * 2];
                    mma_fp16(acc[mt][nt], ah[mt], bhp);
                    mma_fp16(acc[mt][nt], ah[mt], blp);
                }
        }
    };

    auto doEpi = [&](int j) {
        const int m0 = m0_of(j);
        const float* sB = (const float*)smem;
        const int g = lane >> 2, t2 = lane & 3;
#pragma unroll
        for (int mt = 0; mt < 2; mt++)
#pragma unroll
            for (int nt = 0; nt < 4; nt++) {
                int col = wnn + nt * 8 + 2 * t2;          // 0..63 in half
                float b0 = sB[nh * 64 + col];
                float b1 = sB[nh * 64 + col + 1];
#pragma unroll
                for (int h = 0; h < 2; h++) {
                    size_t row = (size_t)m0 + wm + mt * 16 + g + h * 8;
                    float v0 = fast_tanh(acc[mt][nt][h * 2 + 0] + b0);
                    float v1 = fast_tanh(acc[mt][nt][h * 2 + 1] + b1);
                    *(uint32_t*)(Aout + row * 128 + nh * 64 + col) = packh2(v0, v1);
                }
            }
#pragma unroll
        for (int mt = 0; mt < 2; mt++)
#pragma unroll
            for (int nt = 0; nt < 4; nt++)
#pragma unroll
                for (int q = 0; q < 4; q++) acc[mt][nt][q] = 0.0f;
    };

    if (first) {
        // =================== gather level (register prefetch) ===============
        const int gr = tid >> 1, gh = tid & 1;     // row 0..127, col half
        float4 R[8];
        int2 RTcur, RTnext;

        auto tokLd = [&](int t) -> int2 {
            long long tileIdx = blockIdx.x + (long long)t * grid;
            if (tileIdx >= tiles) return make_int2(0, 0);
            long long bi = (tileIdx >> 1) * 256 + 2 * gr;   // m-tile rows
            int a, b;
            if (tok64) {
                a = (int)((const long long*)tokens_raw)[bi];
                b = (int)((const long long*)tokens_raw)[bi + 1];
            } else {
                int2 v = ((const int2*)tokens_raw)[bi >> 1];
                a = v.x; b = v.y;
            }
            if ((unsigned)a >= 100000u) a = 0;
            if ((unsigned)b >= 100000u) b = 0;
            return make_int2(a, b);
        };
        auto gatherLd = [&](int c, int tok) {
            const float4* src = (const float4*)emb + (size_t)tok * 32
                                + (c & 1) * 16 + gh * 8;
#pragma unroll
            for (int i = 0; i < 8; i++) R[i] = __ldg(src + i);
        };
        auto gatherSt = [&](int j) {
            unsigned char* buf = smem + SM_A + (j % 3) * 16384;
#pragma unroll
            for (int i = 0; i < 4; i++) {
                uint4 q;
                q.x = packh2(R[2 * i].x, R[2 * i].y);
                q.y = packh2(R[2 * i].z, R[2 * i].w);
                q.z = packh2(R[2 * i + 1].x, R[2 * i + 1].y);
                q.w = packh2(R[2 * i + 1].z, R[2 * i + 1].w);
                *(uint4*)(buf + swz(gr, gh * 4 + i)) = q;
            }
        };

        RTcur = tokLd(0);
        RTnext = tokLd(1);
        gatherLd(0, RTcur.x); gatherSt(0);
        gatherLd(1, RTcur.x); gatherSt(1);
        gatherLd(2, RTcur.y);
        cpa_wait0();                              // W resident
        __syncthreads();

        for (int j = 0; j < J; j++) {
            doMMA(j);
            __syncthreads();
            if (j + 2 < J) gatherSt(j + 2);       // R holds chunk j+2
            int jj = j + 3;
            if (jj < J) {
                if ((jj & 3) == 0) { RTcur = RTnext; RTnext = tokLd((jj >> 2) + 1); }
                gatherLd(jj & 3, ((jj & 3) >> 1) ? RTcur.y : RTcur.x);
            }
            if ((j & 3) == 3) doEpi(j);
        }
    } else {
        // =================== cp.async level (depth-3 ring) ==================
        auto stageA = [&](int j) {
            const int m0 = m0_of(j);
            const int c = j & 3;
            uint32_t dst = sb + SM_A + (j % 3) * 16384;
#pragma unroll
            for (int i = 0; i < 4; i++) {
                int idx = i * 256 + tid;
                int r = idx >> 3, s = idx & 7;
                size_t src = (size_t)(m0 + r) * 256 + c * 64 + s * 8;
                cpaA16(dst + swz(r, s), Ain + src);
            }
        };

        stageA(0); cpa_commit();
        if (J > 1) stageA(1); cpa_commit();
        if (J > 2) stageA(2); cpa_commit();

        for (int j = 0; j < J; j++) {
            cpa_wait2();                          // chunk j complete (mine)
            __syncthreads();                      // everyone's
            doMMA(j);
            __syncthreads();                      // buf free for overwrite
            if (j + 3 < J) stageA(j + 3);
            cpa_commit();
            if ((j & 3) == 3) doEpi(j);
        }
    }
}

// classifier: out[b,j] = root[b,:] . W_cls[j,:] + b_cls[j]; one warp per row
__global__ __launch_bounds__(256) void cls_kernel(
    const float* __restrict__ Wc, const float* __restrict__ bc,
    float* __restrict__ out)
{
    int warp = (blockIdx.x * 256 + threadIdx.x) >> 5;
    int lane = threadIdx.x & 31;
    if (warp >= 4096) return;
    size_t base = (size_t)warp * 128;
    float s0 = 0.f, s1 = 0.f, s2 = 0.f;
#pragma unroll
    for (int i = 0; i < 4; i++) {
        int e = lane + i * 32;
        float x = __half2float(gA0[base + e]);
        s0 += x * __ldg(Wc + e);
        s1 += x * __ldg(Wc + 128 + e);
        s2 += x * __ldg(Wc + 256 + e);
    }
#pragma unroll
    for (int o = 16; o; o >>= 1) {
        s0 += __shfl_xor_sync(0xffffffffu, s0, o);
        s1 += __shfl_xor_sync(0xffffffffu, s1, o);
        s2 += __shfl_xor_sync(0xffffffffu, s2, o);
    }
    if (lane == 0) {
        out[warp * 3 + 0] = s0 + __ldg(bc + 0);
        out[warp * 3 + 1] = s1 + __ldg(bc + 1);
        out[warp * 3 + 2] = s2 + __ldg(bc + 2);
    }
}

extern "C" void kernel_launch(void* const* d_in, const int* in_sizes, int n_in,
                              void* d_out, int out_size)
{
    const void* tokens = d_in[0];
    const float* emb = (const float*)d_in[1];
    const float* Wt  = (const float*)d_in[2];
    const float* bt  = (const float*)d_in[3];
    const float* Wc  = (const float*)d_in[4];
    const float* bc  = (const float*)d_in[5];
    float* out = (float*)d_out;

    cudaFuncSetAttribute(tree_level_kernel,
                         cudaFuncAttributeMaxDynamicSharedMemorySize, SMEM_BYTES);

    detect_tok_kernel<<<1, 32>>>((const unsigned int*)tokens);
    wsplit_kernel<<<128, 256>>>(Wt);

    // mtiles per level; tiles = 2*mtiles (N-split); grid = min(tiles, 296)
    const int mt[7] = {2048, 1024, 512, 256, 128, 64, 32};
    int flip = 1;
    for (int l = 0; l < 7; l++) {
        int tiles = 2 * mt[l];
        int grid = tiles < 296 ? tiles : 296;
        tree_level_kernel<<<grid, 256, SMEM_BYTES>>>(tokens, emb, bt,
                                                     l == 0 ? 1 : 0, flip, mt[l]);
        flip ^= 1;
    }
    cls_kernel<<<512, 256>>>(Wc, bc, out);
}

// round 15
// speedup vs baseline: 1.2535x; 1.2535x over previous
#include <cuda_runtime.h>
#include <cuda_fp16.h>
#include <cstdint>

// ---------------------------------------------------------------------------
// Tree NN as 7 GEMMs: X_{l+1}[M,128] = tanh(X_l.view(M,256) @ W^T + b).
// concat(left,right) == reinterpret of row-major [2M,128] as [M,256].
// Precision: activations fp16, W split fp16 hi/lo: D = A*Wh + A*Wl (f32 acc).
// R14: ONE pipeline style for all levels (the measured-fastest one):
//   register-pipelined LDG -> STS into a depth-3 smem ring (no cp.async for A;
//   cp.async only for the once-per-CTA resident W = 128KB).
// M_TILE=128, N=128, 512 threads (16 warps, 4x4 grid of 32x32 warp tiles),
// 1 CTA/SM, multi-tile loop with grid = min(mtiles, 148).
// (tcgen05 unavailable: harness compiles for plain sm_103.)
// ---------------------------------------------------------------------------

#define SM_W    512                       // 8 planes x 16384 B (4 chunks, hi/lo)
#define SM_A    (SM_W + 131072)           // 3 bufs x 16384 B
#define SMEM_BYTES (SM_A + 3 * 16384)     // 180736 B -> 1 CTA/SM

__device__ __half gA0[262144u * 128u];    // 64 MiB: L1,3,5,7 outputs
__device__ __half gA1[131072u * 128u];    // 32 MiB: L2,4,6 outputs
__device__ __half gWh[128 * 256];
__device__ __half gWl[128 * 256];
__device__ int g_tok64;

__global__ void detect_tok_kernel(const unsigned int* __restrict__ t) {
    if (threadIdx.x == 0) {
        int all_zero = 1;
        for (int i = 1; i < 256; i += 2) all_zero &= (t[i] == 0u);
        g_tok64 = all_zero;
    }
}
__global__ void wsplit_kernel(const float* __restrict__ Wt) {
    int i = blockIdx.x * 256 + threadIdx.x;
    if (i < 128 * 256) {
        float v = Wt[i];
        __half h = __float2half_rn(v);
        gWh[i] = h;
        gWl[i] = __float2half_rn(v - __half2float(h));
    }
}

__device__ __forceinline__ float fast_tanh(float x) {
    float e = __expf(2.0f * x);
    return 1.0f - __fdividef(2.0f, e + 1.0f);
}
__device__ __forceinline__ uint32_t packh2(float x0, float x1) {
    __half h0 = __float2half_rn(x0), h1 = __float2half_rn(x1);
    return (uint32_t)__half_as_ushort(h0) | ((uint32_t)__half_as_ushort(h1) << 16);
}
__device__ __forceinline__ void mma_fp16(float* d, const uint32_t* a,
                                         const uint32_t* b) {
    asm volatile(
        "mma.sync.aligned.m16n8k16.row.col.f32.f16.f16.f32 "
        "{%0,%1,%2,%3}, {%4,%5,%6,%7}, {%8,%9}, {%0,%1,%2,%3};\n"
        : "+f"(d[0]), "+f"(d[1]), "+f"(d[2]), "+f"(d[3])
        : "r"(a[0]), "r"(a[1]), "r"(a[2]), "r"(a[3]), "r"(b[0]), "r"(b[1]));
}
__device__ __forceinline__ void ldsm4(uint32_t* r, uint32_t saddr) {
    asm volatile(
        "ldmatrix.sync.aligned.m8n8.x4.shared.b16 {%0,%1,%2,%3}, [%4];\n"
        : "=r"(r[0]), "=r"(r[1]), "=r"(r[2]), "=r"(r[3]) : "r"(saddr));
}
__device__ __forceinline__ void cpaW16(uint32_t dst, const void* src) {
    asm volatile("cp.async.ca.shared.global [%0], [%1], 16;" :: "r"(dst), "l"(src));
}
__device__ __forceinline__ void cpa_commit() { asm volatile("cp.async.commit_group;"); }
__device__ __forceinline__ void cpa_wait0() { asm volatile("cp.async.wait_group 0;"); }

// swizzled byte offset inside a 128B-row plane: row r, 16B slot s
__device__ __forceinline__ uint32_t swz(int r, int s) {
    return (uint32_t)(r * 128 + ((s ^ (r & 7)) * 16));
}

// ---------------------------------------------------------------------------
// One level. grid = min(mtiles, 148). Each CTA loops m-tiles (128 rows).
__global__ __launch_bounds__(512, 1) void tree_level_kernel(
    const void* __restrict__ tokens_raw,
    const float* __restrict__ emb,
    const float* __restrict__ bias,
    int first, int flip, int mtiles)
{
    extern __shared__ __align__(16) unsigned char smem[];
    const uint32_t sb = (uint32_t)__cvta_generic_to_shared(smem);
    const int tid  = threadIdx.x;
    const int lane = tid & 31;
    const int w    = tid >> 5;
    const int grid = gridDim.x;
    const int tok64 = g_tok64;

    const __half* Ain = flip ? gA1 : gA0;
    __half* Aout      = flip ? gA0 : gA1;

    int nT = 0;
    for (int t = blockIdx.x; t < mtiles; t += grid) nT++;
    const int J = nT * 4;

    // ---- bias + resident W (staged once; only cp.async group) ----
    if (tid < 128) ((float*)smem)[tid] = bias[tid];
#pragma unroll
    for (int t = 0; t < 16; t++) {
        int i = t * 512 + tid;                 // 8192 16B chunks
        int cp = i >> 10, rem = i & 1023;      // cp = chunk*2 + lo
        int r = rem >> 3, s = rem & 7;
        const __half* src = ((cp & 1) ? gWl : gWh)
                          + r * 256 + (cp >> 1) * 64 + s * 8;
        cpaW16(sb + SM_W + cp * 16384 + swz(r, s), src);
    }
    cpa_commit();

    // warp geometry: 4 warps M x 4 warps N, warp tile 32x32
    const int wm = (w & 3) * 32;
    const int wn = (w >> 2) * 32;
    const int la_row = lane & 15;
    const int la_s   = lane >> 4;
    const int lb_n   = ((lane >> 4) << 3) + (lane & 7);
    const int lb_s   = (lane >> 3) & 1;

    // A staging thread map: row gr (0..127), quarter gq (slots 2gq, 2gq+1)
    const int gr = tid >> 2, gq = tid & 3;

    float acc[2][4][4] = {};

    auto doMMA = [&](int j) {
        const int c = j & 3;
        const uint32_t aB = sb + SM_A + (j % 3) * 16384;
        const uint32_t bH = sb + SM_W + (c * 2) * 16384;
        const uint32_t bL = bH + 16384;
#pragma unroll
        for (int ks = 0; ks < 4; ks++) {
            uint32_t ah[2][4], bh[2][4], bl[2][4];
#pragma unroll
            for (int mt = 0; mt < 2; mt++)
                ldsm4(ah[mt], aB + swz(wm + mt * 16 + la_row, ks * 2 + la_s));
#pragma unroll
            for (int pr = 0; pr < 2; pr++) {
                int r = wn + pr * 16 + lb_n;
                ldsm4(bh[pr], bH + swz(r, ks * 2 + lb_s));
                ldsm4(bl[pr], bL + swz(r, ks * 2 + lb_s));
            }
#pragma unroll
            for (int mt = 0; mt < 2; mt++)
#pragma unroll
                for (int nt = 0; nt < 4; nt++) {
                    const uint32_t* bhp = &bh[nt >> 1][(nt & 1) * 2];
                    const uint32_t* blp = &bl[nt >> 1][(nt & 1) * 2];
                    mma_fp16(acc[mt][nt], ah[mt], bhp);
                    mma_fp16(acc[mt][nt], ah[mt], blp);
                }
        }
    };

    auto doEpi = [&](int j) {
        const int m0 = (blockIdx.x + (j >> 2) * grid) * 128;
        const float* sB = (const float*)smem;
        const int g = lane >> 2, t2 = lane & 3;
#pragma unroll
        for (int mt = 0; mt < 2; mt++)
#pragma unroll
            for (int nt = 0; nt < 4; nt++) {
                int col = wn + nt * 8 + 2 * t2;
                float b0 = sB[col], b1 = sB[col + 1];
#pragma unroll
                for (int h = 0; h < 2; h++) {
                    size_t row = (size_t)m0 + wm + mt * 16 + g + h * 8;
                    float v0 = fast_tanh(acc[mt][nt][h * 2 + 0] + b0);
                    float v1 = fast_tanh(acc[mt][nt][h * 2 + 1] + b1);
                    *(uint32_t*)(Aout + row * 128 + col) = packh2(v0, v1);
                }
            }
#pragma unroll
        for (int mt = 0; mt < 2; mt++)
#pragma unroll
            for (int nt = 0; nt < 4; nt++)
#pragma unroll
                for (int q = 0; q < 4; q++) acc[mt][nt][q] = 0.0f;
    };

    if (first) {
        // ============ gather level: token-indirected LDG pipeline ===========
        float4 R[4];
        int2 RTcur, RTnext;
        auto tokLd = [&](int t) -> int2 {
            long long tileIdx = blockIdx.x + (long long)t * grid;
            if (tileIdx >= mtiles) return make_int2(0, 0);
            long long bi = (tileIdx * 128 + gr) * 2;
            int a, b;
            if (tok64) {
                a = (int)((const long long*)tokens_raw)[bi];
                b = (int)((const long long*)tokens_raw)[bi + 1];
            } else {
                int2 v = ((const int2*)tokens_raw)[bi >> 1];
                a = v.x; b = v.y;
            }
            if ((unsigned)a >= 100000u) a = 0;
            if ((unsigned)b >= 100000u) b = 0;
            return make_int2(a, b);
        };
        auto aLd = [&](int j) {
            int c = j & 3;
            int tok = (c >> 1) ? RTcur.y : RTcur.x;
            const float4* src = (const float4*)emb + (size_t)tok * 32
                                + (c & 1) * 16 + gq * 4;
#pragma unroll
            for (int i = 0; i < 4; i++) R[i] = __ldg(src + i);
        };
        auto aSt = [&](int j) {
            unsigned char* buf = smem + SM_A + (j % 3) * 16384;
            uint4 q0, q1;
            q0.x = packh2(R[0].x, R[0].y); q0.y = packh2(R[0].z, R[0].w);
            q0.z = packh2(R[1].x, R[1].y); q0.w = packh2(R[1].z, R[1].w);
            q1.x = packh2(R[2].x, R[2].y); q1.y = packh2(R[2].z, R[2].w);
            q1.z = packh2(R[3].x, R[3].y); q1.w = packh2(R[3].z, R[3].w);
            *(uint4*)(buf + swz(gr, gq * 2)) = q0;
            *(uint4*)(buf + swz(gr, gq * 2 + 1)) = q1;
        };

        RTcur = tokLd(0); RTnext = tokLd(1);
        aLd(0); aSt(0);
        aLd(1); aSt(1);
        aLd(2);
        cpa_wait0();                           // W resident
        __syncthreads();

        for (int j = 0; j < J; j++) {
            doMMA(j);
            __syncthreads();
            if (j + 2 < J) aSt(j + 2);         // R holds chunk j+2
            int jj = j + 3;
            if (jj < J) {
                if ((jj & 3) == 0) { RTcur = RTnext; RTnext = tokLd((jj >> 2) + 1); }
                aLd(jj);
            }
            if ((j & 3) == 3) doEpi(j);
        }
    } else {
        // ============ dense level: plain LDG pipeline (same shape) ==========
        uint4 RU[2];
        auto aLd = [&](int j) {
            const int m0 = (blockIdx.x + (j >> 2) * grid) * 128;
            const int c = j & 3;
            const uint4* src = (const uint4*)(Ain + (size_t)(m0 + gr) * 256
                                              + c * 64 + gq * 16);
            RU[0] = __ldg(src);
            RU[1] = __ldg(src + 1);
        };
        auto aSt = [&](int j) {
            unsigned char* buf = smem + SM_A + (j % 3) * 16384;
            *(uint4*)(buf + swz(gr, gq * 2)) = RU[0];
            *(uint4*)(buf + swz(gr, gq * 2 + 1)) = RU[1];
        };

        aLd(0); aSt(0);
        aLd(1); aSt(1);
        aLd(2);
        cpa_wait0();                           // W resident
        __syncthreads();

        for (int j = 0; j < J; j++) {
            doMMA(j);
            __syncthreads();
            if (j + 2 < J) aSt(j + 2);
            if (j + 3 < J) aLd(j + 3);
            if ((j & 3) == 3) doEpi(j);
        }
    }
}

// classifier: out[b,j] = root[b,:] . W_cls[j,:] + b_cls[j]; one warp per row
__global__ __launch_bounds__(256) void cls_kernel(
    const float* __restrict__ Wc, const float* __restrict__ bc,
    float* __restrict__ out)
{
    int warp = (blockIdx.x * 256 + threadIdx.x) >> 5;
    int lane = threadIdx.x & 31;
    if (warp >= 4096) return;
    size_t base = (size_t)warp * 128;
    float s0 = 0.f, s1 = 0.f, s2 = 0.f;
#pragma unroll
    for (int i = 0; i < 4; i++) {
        int e = lane + i * 32;
        float x = __half2float(gA0[base + e]);
        s0 += x * __ldg(Wc + e);
        s1 += x * __ldg(Wc + 128 + e);
        s2 += x * __ldg(Wc + 256 + e);
    }
#pragma unroll
    for (int o = 16; o; o >>= 1) {
        s0 += __shfl_xor_sync(0xffffffffu, s0, o);
        s1 += __shfl_xor_sync(0xffffffffu, s1, o);
        s2 += __shfl_xor_sync(0xffffffffu, s2, o);
    }
    if (lane == 0) {
        out[warp * 3 + 0] = s0 + __ldg(bc + 0);
        out[warp * 3 + 1] = s1 + __ldg(bc + 1);
        out[warp * 3 + 2] = s2 + __ldg(bc + 2);
    }
}

extern "C" void kernel_launch(void* const* d_in, const int* in_sizes, int n_in,
                              void* d_out, int out_size)
{
    const void* tokens = d_in[0];
    const float* emb = (const float*)d_in[1];
    const float* Wt  = (const float*)d_in[2];
    const float* bt  = (const float*)d_in[3];
    const float* Wc  = (const float*)d_in[4];
    const float* bc  = (const float*)d_in[5];
    float* out = (float*)d_out;

    cudaFuncSetAttribute(tree_level_kernel,
                         cudaFuncAttributeMaxDynamicSharedMemorySize, SMEM_BYTES);

    detect_tok_kernel<<<1, 32>>>((const unsigned int*)tokens);
    wsplit_kernel<<<128, 256>>>(Wt);

    const int mt[7] = {2048, 1024, 512, 256, 128, 64, 32};
    int flip = 1;
    for (int l = 0; l < 7; l++) {
        int grid = mt[l] < 148 ? mt[l] : 148;
        tree_level_kernel<<<grid, 512, SMEM_BYTES>>>(tokens, emb, bt,
                                                     l == 0 ? 1 : 0, flip, mt[l]);
        flip ^= 1;
    }
    cls_kernel<<<512, 256>>>(Wc, bc, out);
}